// round 7
// baseline (speedup 1.0000x reference)
#include <cuda_runtime.h>
#include <cuda_fp16.h>
#include <math.h>
#include <stdint.h>

#define NROWS 8192
#define DDIM  128
#define NT    64          // 8192/128 tiles per side
#define NPAIR 2080        // 64*65/2

// Scratch (__device__ globals: allocation-free rule)
__device__ uint8_t g_h1q[NROWS * DDIM];   // e4m3 of c*normalized h1, c=sqrt(5*log2 e)
__device__ uint8_t g_h2q[NROWS * DDIM];
__device__ float g_R[4 * NROWS];          // [R11 | R12row | R12col | R22]
__device__ float g_diag[NROWS];

// ---------------------------------------------------------------------------
__device__ __forceinline__ uint32_t smem_u32(const void* p) {
    uint32_t a;
    asm("{ .reg .u64 t; cvta.to.shared.u64 t, %1; cvt.u32.u64 %0, t; }"
        : "=r"(a) : "l"(p));
    return a;
}

__device__ __forceinline__ void ldsm_x4(uint32_t& r0, uint32_t& r1,
                                        uint32_t& r2, uint32_t& r3, uint32_t addr) {
    asm volatile("ldmatrix.sync.aligned.m8n8.x4.shared.b16 {%0,%1,%2,%3}, [%4];"
                 : "=r"(r0), "=r"(r1), "=r"(r2), "=r"(r3) : "r"(addr));
}

__device__ __forceinline__ void mma_fp8(float* d, const uint32_t* a, const uint32_t* b) {
    asm volatile(
        "mma.sync.aligned.m16n8k32.row.col.f32.e4m3.e4m3.f32 "
        "{%0,%1,%2,%3}, {%4,%5,%6,%7}, {%8,%9}, {%0,%1,%2,%3};"
        : "+f"(d[0]), "+f"(d[1]), "+f"(d[2]), "+f"(d[3])
        : "r"(a[0]), "r"(a[1]), "r"(a[2]), "r"(a[3]), "r"(b[0]), "r"(b[1]));
}

__device__ __forceinline__ uint32_t pack_e4m3x4(float e0, float e1, float e2, float e3) {
    uint32_t r;
    asm("{ .reg .b16 lo, hi;\n\t"
        "cvt.rn.satfinite.e4m3x2.f32 lo, %2, %1;\n\t"
        "cvt.rn.satfinite.e4m3x2.f32 hi, %4, %3;\n\t"
        "mov.b32 %0, {lo, hi}; }"
        : "=r"(r) : "f"(e0), "f"(e1), "f"(e2), "f"(e3));
    return r;
}

// ---------------------------------------------------------------------------
// Row-normalize -> e4m3 scaled by C = sqrt(5*log2(e)); exact fp32 diag;
// zero g_R and out.  acc = 5*log2(e)*s, so exp(5s) = 2^acc.
// ---------------------------------------------------------------------------
__global__ void norm_kernel(const float* __restrict__ h1,
                            const float* __restrict__ h2,
                            float* __restrict__ out) {
    int gt   = blockIdx.x * blockDim.x + threadIdx.x;
    int w    = gt >> 5;
    int lane = gt & 31;

    if (gt < 4 * NROWS) g_R[gt] = 0.0f;
    if (gt == 0) out[0] = 0.0f;
    if (w >= NROWS) return;

    float4 v1 = ((const float4*)(h1 + (size_t)w * DDIM))[lane];
    float4 v2 = ((const float4*)(h2 + (size_t)w * DDIM))[lane];

    float ss1 = v1.x*v1.x + v1.y*v1.y + v1.z*v1.z + v1.w*v1.w;
    float ss2 = v2.x*v2.x + v2.y*v2.y + v2.z*v2.z + v2.w*v2.w;
    float dt  = v1.x*v2.x + v1.y*v2.y + v1.z*v2.z + v1.w*v2.w;

    #pragma unroll
    for (int m = 16; m > 0; m >>= 1) {
        ss1 += __shfl_xor_sync(0xffffffffu, ss1, m);
        ss2 += __shfl_xor_sync(0xffffffffu, ss2, m);
        dt  += __shfl_xor_sync(0xffffffffu, dt,  m);
    }

    const float C = 2.6857914f;   // sqrt(5*log2(e))
    float in1 = 1.0f / fmaxf(sqrtf(ss1), 1e-12f);
    float in2 = 1.0f / fmaxf(sqrtf(ss2), 1e-12f);
    float s1 = C * in1, s2 = C * in2;

    ((uint32_t*)(g_h1q + (size_t)w * DDIM))[lane] =
        pack_e4m3x4(v1.x*s1, v1.y*s1, v1.z*s1, v1.w*s1);
    ((uint32_t*)(g_h2q + (size_t)w * DDIM))[lane] =
        pack_e4m3x4(v2.x*s2, v2.y*s2, v2.z*s2, v2.w*s2);

    if (lane == 0) g_diag[w] = dt * in1 * in2;
}

// ---------------------------------------------------------------------------
// Pair-CTA kernel, occupancy 3, f16x2 epilogue. One CTA per tile pair (I<=J).
// Two passes sharing A-fragments:
//   pass0 (A=h1[I]): q0: B=h1[J] (S11)  q1: B=h2[J] (S12)
//   pass1 (A=h2[I]): q0: B=h2[J] (S22)  q1: B=h1[J] (S21, offd only)
// Row sums -> I-side, col sums -> J-side (S21 swaps R12 row/col roles).
// ---------------------------------------------------------------------------
#define SM_TILE 16384
#define SM_TOTAL (4 * SM_TILE)

__global__ void __launch_bounds__(256, 3) mma_exp_kernel() {
    extern __shared__ char smem[];
    const uint32_t sb = smem_u32(smem);

    int tid  = threadIdx.x;
    int wid  = tid >> 5;
    int lane = tid & 31;

    // Decode triangular pair index -> (I, J), I<=J
    int p = blockIdx.x, I = 0;
    while (p >= NT - I) { p -= NT - I; I++; }
    int J = I + p;
    bool offd = (J > I);

    // ---- Load 4 tiles (h1[I], h2[I], h1[J], h2[J]) into swizzled SMEM
    {
        const uint4* base[4] = {
            (const uint4*)(g_h1q + (size_t)I * 128 * DDIM),
            (const uint4*)(g_h2q + (size_t)I * 128 * DDIM),
            (const uint4*)(g_h1q + (size_t)J * 128 * DDIM),
            (const uint4*)(g_h2q + (size_t)J * 128 * DDIM)
        };
        #pragma unroll
        for (int it = 0; it < 16; it++) {
            int tile = it >> 2;
            int lidx = tid + (it & 3) * 256;
            int r = lidx >> 3, c = lidx & 7;
            uint32_t off = (uint32_t)tile * SM_TILE + (uint32_t)r * 128u
                         + (uint32_t)((c ^ (r & 7)) << 4);
            *(uint4*)(smem + off) = base[tile][lidx];
        }
    }
    __syncthreads();

    int wm = wid >> 2;          // 0..1  (M)
    int wn = wid & 3;           // 0..3  (N)
    int a_r  = wm * 64 + (lane & 15);
    int a_cp = lane >> 4;
    int b_r  = wn * 32 + ((lane >> 4) << 3) + (lane & 7);
    int b_cp = (lane >> 3) & 1;

    #pragma unroll 1
    for (int pass = 0; pass < 2; pass++) {
        uint32_t As  = (uint32_t)pass * SM_TILE;
        uint32_t Bs0 = (pass == 0) ? 2u * SM_TILE : 3u * SM_TILE;
        uint32_t Bs1 = (pass == 0) ? 3u * SM_TILE : 2u * SM_TILE;

        float *rowp0, *colp0, *rowp1, *colp1;
        if (pass == 0) {
            rowp0 = g_R + I*128;             colp0 = g_R + J*128;             // S11
            rowp1 = g_R + NROWS + I*128;     colp1 = g_R + 2*NROWS + J*128;   // S12
        } else {
            rowp0 = g_R + 3*NROWS + I*128;   colp0 = g_R + 3*NROWS + J*128;   // S22
            rowp1 = g_R + 2*NROWS + I*128;   colp1 = g_R + NROWS + J*128;     // S21
        }
        int nq = (pass == 1 && !offd) ? 1 : 2;

        __half2 cp[2][4];
        #pragma unroll
        for (int q = 0; q < 2; q++)
            #pragma unroll
            for (int nt = 0; nt < 4; nt++) cp[q][nt] = __half2half2(__ushort_as_half(0));

        #pragma unroll
        for (int mt = 0; mt < 4; mt++) {
            // A fragments for this strip (shared by both q GEMMs)
            uint32_t a[4][4];
            int r = a_r + mt * 16;
            #pragma unroll
            for (int ks = 0; ks < 4; ks++) {
                uint32_t addr = sb + As + (uint32_t)r * 128u
                              + (uint32_t)(((ks * 2 + a_cp) ^ (r & 7)) << 4);
                ldsm_x4(a[ks][0], a[ks][1], a[ks][2], a[ks][3], addr);
            }

            #pragma unroll
            for (int q = 0; q < 2; q++) {
                if (q >= nq) break;
                uint32_t Bs = q ? Bs1 : Bs0;

                float acc[4][4];
                #pragma unroll
                for (int nt = 0; nt < 4; nt++)
                    #pragma unroll
                    for (int v = 0; v < 4; v++) acc[nt][v] = 0.0f;

                #pragma unroll
                for (int ks = 0; ks < 4; ks++) {
                    uint32_t b[4][2];
                    #pragma unroll
                    for (int np = 0; np < 2; np++) {
                        int br = b_r + np * 16;
                        uint32_t addr = sb + Bs + (uint32_t)br * 128u
                                      + (uint32_t)(((ks * 2 + b_cp) ^ (br & 7)) << 4);
                        ldsm_x4(b[np*2][0], b[np*2][1], b[np*2+1][0], b[np*2+1][1], addr);
                    }
                    #pragma unroll
                    for (int nt = 0; nt < 4; nt++)
                        mma_fp8(acc[nt], a[ks], b[nt]);
                }

                // ---- f16x2 epilogue: e = 2^acc
                __half2 rpA = __half2half2(__ushort_as_half(0));
                __half2 rpB = rpA;
                #pragma unroll
                for (int nt = 0; nt < 4; nt++) {
                    __half2 e01 = h2exp2(__float22half2_rn(make_float2(acc[nt][0], acc[nt][1])));
                    __half2 e23 = h2exp2(__float22half2_rn(make_float2(acc[nt][2], acc[nt][3])));
                    rpA = __hadd2(rpA, e01);
                    rpB = __hadd2(rpB, e23);
                    __half2 cs = __hadd2(e01, e23);          // (e0+e2, e1+e3) = col pair
                    cp[q][nt] = __hadd2(cp[q][nt], cs);
                }
                // Row reduce across the 4 column-threads
                rpA = __hadd2(rpA, __shfl_xor_sync(0xffffffffu, rpA, 1));
                rpA = __hadd2(rpA, __shfl_xor_sync(0xffffffffu, rpA, 2));
                rpB = __hadd2(rpB, __shfl_xor_sync(0xffffffffu, rpB, 1));
                rpB = __hadd2(rpB, __shfl_xor_sync(0xffffffffu, rpB, 2));
                if ((lane & 3) == 0) {
                    float* rp = q ? rowp1 : rowp0;
                    int r0 = wm * 64 + mt * 16 + (lane >> 2);
                    atomicAdd(&rp[r0],     __low2float(rpA) + __high2float(rpA));
                    atomicAdd(&rp[r0 + 8], __low2float(rpB) + __high2float(rpB));
                }
            }
        }

        // ---- Column sums: q0 only if offd (S11/S22); q1 always (S12/S21)
        #pragma unroll
        for (int q = 0; q < 2; q++) {
            bool docol = (q == 0) ? offd : (nq == 2);
            if (!docol) continue;
            float* cpp = q ? colp1 : colp0;
            #pragma unroll
            for (int nt = 0; nt < 4; nt++) {
                __half2 v = cp[q][nt];
                v = __hadd2(v, __shfl_xor_sync(0xffffffffu, v, 4));
                v = __hadd2(v, __shfl_xor_sync(0xffffffffu, v, 8));
                v = __hadd2(v, __shfl_xor_sync(0xffffffffu, v, 16));
                if (lane < 4) {
                    int c0 = wn * 32 + lane * 2 + nt * 8;
                    atomicAdd(&cpp[c0],     __low2float(v));
                    atomicAdd(&cpp[c0 + 1], __high2float(v));
                }
            }
        }
    }
}

// ---------------------------------------------------------------------------
// Final scalar: 32 blocks x 256 threads, one row per thread.
// ---------------------------------------------------------------------------
__global__ void final_kernel(float* out) {
    __shared__ float sm[256];
    int t = threadIdx.x;
    int i = blockIdx.x * 256 + t;
    const float E5 = 148.4131591f;   // exp(1/tau), tau = 0.2

    float n1 = g_R[i]             + g_R[NROWS + i]     - E5;
    float n2 = g_R[3 * NROWS + i] + g_R[2 * NROWS + i] - E5;
    float s  = 0.5f * (logf(n1) + logf(n2)) - 5.0f * g_diag[i];

    sm[t] = s;
    __syncthreads();
    #pragma unroll
    for (int o = 128; o > 0; o >>= 1) {
        if (t < o) sm[t] += sm[t + o];
        __syncthreads();
    }
    if (t == 0) atomicAdd(out, sm[0] * (1.0f / NROWS));
}

// ---------------------------------------------------------------------------
extern "C" void kernel_launch(void* const* d_in, const int* in_sizes, int n_in,
                              void* d_out, int out_size) {
    const float* h1 = (const float*)d_in[0];
    const float* h2 = (const float*)d_in[1];
    float* out = (float*)d_out;

    cudaFuncSetAttribute(mma_exp_kernel,
                         cudaFuncAttributeMaxDynamicSharedMemorySize, SM_TOTAL);

    norm_kernel<<<(NROWS * 32) / 256, 256>>>(h1, h2, out);
    mma_exp_kernel<<<NPAIR, 256, SM_TOTAL>>>();
    final_kernel<<<NROWS / 256, 256>>>(out);
}